// round 10
// baseline (speedup 1.0000x reference)
#include <cuda_runtime.h>
#include <cuda_bf16.h>
#include <cstdint>

// ---------------------------------------------------------------------------
// GCNArchEmbedder via mma.sync bf16 (HMMA), 3-pass hi/lo fp32 emulation.
// R10: persistent warp-specialized CTAs (148 x 512thr) + direct-sum producer
//   using fused U01 table (one row per node embedding, built once per CTA).
//   warps 8-15 produce A-fragments (short chains), warps 0-7 consume (mma).
// ---------------------------------------------------------------------------

#define NUM_PRIM   8
#define OPD        48
#define OPH        48
#define GD         128
#define ROWS       65536
#define TILE_M     64
#define NTILES     (ROWS / TILE_M)     // 1024
#define NCTAS      148
#define U01S       130     // fused-table k-stride (floats): full bank spread

// table rows: 0..7 U0''[p] (=U0+Uc), 8..15 U1[p], 16..17 H1init
__device__ float g_tab[18 * GD];
// W2 fragments: idx = (ks*16 + ntile)*32 + lane ; {b0hi, b1hi, b0lo, b1lo}
__device__ uint4 g_bfrag[4096];

// low half = first arg (k-even element)
__device__ __forceinline__ uint32_t bf16x2(float lo, float hi) {
    uint32_t r; asm("cvt.rn.bf16x2.f32 %0, %1, %2;" : "=r"(r) : "f"(hi), "f"(lo)); return r;
}
__device__ __forceinline__ float bf_lo(uint32_t u) { return __uint_as_float(u << 16); }
__device__ __forceinline__ float bf_hi(uint32_t u) { return __uint_as_float(u & 0xffff0000u); }

__device__ __forceinline__ void mma_bf16(float* d, const uint32_t* a,
                                         uint32_t b0, uint32_t b1) {
    asm volatile(
        "mma.sync.aligned.m16n8k16.row.col.f32.bf16.bf16.f32 "
        "{%0,%1,%2,%3}, {%4,%5,%6,%7}, {%8,%9}, {%0,%1,%2,%3};"
        : "+f"(d[0]), "+f"(d[1]), "+f"(d[2]), "+f"(d[3])
        : "r"(a[0]), "r"(a[1]), "r"(a[2]), "r"(a[3]), "r"(b0), "r"(b1));
}

__device__ __forceinline__ uint32_t smem_u32(const void* p) {
    uint32_t a;
    asm("{ .reg .u64 t; cvta.to.shared.u64 t, %1; cvt.u32.u64 %0, t; }" : "=r"(a) : "l"(p));
    return a;
}
__device__ __forceinline__ void cp_async16(uint32_t saddr, const void* g) {
    asm volatile("cp.async.cg.shared.global [%0], [%1], 16;" :: "r"(saddr), "l"(g) : "memory");
}

// ---------------------------------------------------------------------------
// Prep kernel, <<<33, 256>>> (wide & shallow):
//   blocks 0..15 : (p, which) -> U0''[p] / U1[p]
//   block  16    : H1init rows
//   blocks 17..32: W2 fragment pack
// ---------------------------------------------------------------------------
__global__ void gcn_prep_kernel(const float* __restrict__ init_emb,
                                const float* __restrict__ op_emb,
                                const float* __restrict__ xw,
                                const float* __restrict__ xb,
                                const float* __restrict__ w1,
                                const float* __restrict__ w2) {
    const int b = blockIdx.x;
    const int t = threadIdx.x;

    if (b < 16) {                      // row (which*8 + p) of g_tab
        const int p = b >> 1, which = b & 1;
        __shared__ float T[OPH];
        if (t < OPH) {
            float s0 = 0.f, s1 = 0.f, s2 = 0.f, s3 = 0.f;
            const int db = which * OPD;
            for (int d = 0; d < OPD; d += 4) {
                s0 = fmaf(op_emb[p * OPD + d],     xw[(db + d) * OPH + t],     s0);
                s1 = fmaf(op_emb[p * OPD + d + 1], xw[(db + d + 1) * OPH + t], s1);
                s2 = fmaf(op_emb[p * OPD + d + 2], xw[(db + d + 2) * OPH + t], s2);
                s3 = fmaf(op_emb[p * OPD + d + 3], xw[(db + d + 3) * OPH + t], s3);
            }
            T[t] = (s0 + s1) + (s2 + s3);
        }
        __syncthreads();
        if (t < GD) {
            float s0 = 0.f, s1 = 0.f, u0 = 0.f, u1 = 0.f;
            for (int h = 0; h < OPH; h += 2) {
                float wa = w1[h * GD + t], wb = w1[(h + 1) * GD + t];
                s0 = fmaf(T[h],     wa, s0);
                s1 = fmaf(T[h + 1], wb, s1);
                u0 = fmaf(xb[h],     wa, u0);
                u1 = fmaf(xb[h + 1], wb, u1);
            }
            g_tab[(which * 8 + p) * GD + t] = s0 + s1 + (which == 0 ? (u0 + u1) : 0.f);
        }
    } else if (b == 16) {              // init rows
        __shared__ float Y[2][OPH];
        if (t < 96) {
            const int kk = t / 48, h = t % 48;
            float s0 = xb[h], s1 = 0.f, s2 = 0.f, s3 = 0.f;
            for (int d = 0; d < 2 * OPD; d += 4) {
                s0 = fmaf(init_emb[kk * 2 * OPD + d],     xw[d * OPH + h],       s0);
                s1 = fmaf(init_emb[kk * 2 * OPD + d + 1], xw[(d + 1) * OPH + h], s1);
                s2 = fmaf(init_emb[kk * 2 * OPD + d + 2], xw[(d + 2) * OPH + h], s2);
                s3 = fmaf(init_emb[kk * 2 * OPD + d + 3], xw[(d + 3) * OPH + h], s3);
            }
            Y[kk][h] = (s0 + s1) + (s2 + s3);
        }
        __syncthreads();
        const int kk = t >> 7, f = t & 127;
        float s0 = 0.f, s1 = 0.f;
        for (int h = 0; h < OPH; h += 2) {
            s0 = fmaf(Y[kk][h],     w1[h * GD + f],       s0);
            s1 = fmaf(Y[kk][h + 1], w1[(h + 1) * GD + f], s1);
        }
        g_tab[(16 + kk) * GD + f] = s0 + s1;
    } else {                           // W2 pack
        const int idx = (b - 17) * 256 + t;  // 0..4095
        const int lane = idx & 31;
        const int nt   = (idx >> 5) & 15;
        const int ks   = idx >> 9;
        const int k0 = ks * 16 + (lane & 3) * 2;
        const int n  = nt * 8 + (lane >> 2);
        float w00 = w2[k0 * GD + n];
        float w01 = w2[(k0 + 1) * GD + n];
        float w10 = w2[(k0 + 8) * GD + n];
        float w11 = w2[(k0 + 9) * GD + n];
        uint32_t b0h = bf16x2(w00, w01);
        uint32_t b1h = bf16x2(w10, w11);
        uint32_t b0l = bf16x2(w00 - bf_lo(b0h), w01 - bf_hi(b0h));
        uint32_t b1l = bf16x2(w10 - bf_lo(b1h), w11 - bf_hi(b1h));
        g_bfrag[idx] = make_uint4(b0h, b1h, b0l, b1l);
    }
}

// ---------------------------------------------------------------------------
// Persistent main kernel. smem byte layout:
//   AH[2]  0      (2 x 16384)   [g4][ks8][pos32] uint4, XOR-swizzled pos
//   AL[2]  32768  (2 x 16384)
//   B      65536  (65536)       [ks8][nt16][lane32] uint4 {b0h,b1h,b0l,b1l}
//   U01    131072 (33280)       64 x U01S floats: U0''[o0]+U1[o1]
//   P01    164352 (1024)        H1init rows (2 x 128)
// total 165376 B -> 1 CTA/SM.
// ---------------------------------------------------------------------------
#define SM_AH    0
#define SM_AL    32768
#define SM_B     65536
#define SM_U01   131072
#define SM_P01   164352
#define SMEM_BYTES 165376

__global__ void __launch_bounds__(512, 1)
gcn_main_kernel(const int* __restrict__ archs, float* __restrict__ out) {
    extern __shared__ char smem[];
    float* u01 = (float*)(smem + SM_U01);
    float* p01 = (float*)(smem + SM_P01);

    const int tid  = threadIdx.x;
    const int wid  = tid >> 5;
    const int lane = tid & 31;
    const bool consumer = (wid < 8);

    // ---- one-time staging: B frags (cp.async) + fused U01 table + init ----
    {
        const uint32_t bsm = smem_u32(smem + SM_B);
#pragma unroll
        for (int i = 0; i < 8; i++)
            cp_async16(bsm + (tid + 512 * i) * 16, &g_bfrag[tid + 512 * i]);
        asm volatile("cp.async.commit_group;" ::: "memory");
        for (int idx = tid; idx < 4096; idx += 512) {
            const int pair = idx >> 6;
            const int k2 = idx & 63;
            const int o0 = pair >> 3, o1 = pair & 7;
            float2 a = *(const float2*)(g_tab + o0 * GD + k2 * 2);
            float2 b = *(const float2*)(g_tab + (8 + o1) * GD + k2 * 2);
            *(float2*)(u01 + pair * U01S + k2 * 2) = make_float2(a.x + b.x, a.y + b.y);
        }
        if (tid < 128) {
            float2 v = *(const float2*)(g_tab + 16 * GD + tid * 2);
            *(float2*)(p01 + tid * 2) = v;
        }
        asm volatile("cp.async.wait_group 0;" ::: "memory");
    }
    __syncthreads();

    // consumer constants
    const int rg = (wid >> 2) & 1;
    const int cg = wid & 3;
    const int pos = (lane & 28) | ((lane ^ (lane >> 3)) & 3);
    // producer constants
    const int ptid = tid - 256;
    const int prow = ptid & 63;
    const int pkq  = (ptid >> 6) & 3;

    int prev_t = -1;
    int buf = 0;

    for (int t = blockIdx.x; t < NTILES; t += NCTAS) {
        if (!consumer) {
            // ================= PRODUCE tile t into buf =================
            const int row = prow;
            const int g_  = row >> 4;
            const int r   = row & 7;
            const bool hiRole = ((row & 8) == 0);

            const int4* ap = (const int4*)(archs + ((size_t)t * TILE_M + row) * 16);
            int4 a0v = __ldg(ap), a1v = __ldg(ap + 1);
            int4 a2v = __ldg(ap + 2), a3v = __ldg(ap + 3);
            int pe[8] = {a0v.x, a0v.y, a0v.z, a0v.w, a1v.x, a1v.y, a1v.z, a1v.w};
            int oe[8] = {a2v.x, a2v.y, a2v.z, a2v.w, a3v.x, a3v.y, a3v.z, a3v.w};

            float mmv[4];
#pragma unroll
            for (int s = 0; s < 4; s++) {
                float c = 0.f;
#pragma unroll
                for (int e = 0; e < 8; e++) c += (pe[e] == s + 2) ? 1.f : 0.f;
                mmv[s] = c * 0.25f;
            }

            const float* nd0 = p01;
            const float* nd1 = p01 + GD;
            const float* nd2 = u01 + (oe[0] * 8 + oe[1]) * U01S;
            const float* nd3 = u01 + (oe[2] * 8 + oe[3]) * U01S;
            const float* nd4 = u01 + (oe[4] * 8 + oe[5]) * U01S;
            const float* nd5 = u01 + (oe[6] * 8 + oe[7]) * U01S;

            const float* pa[4];
            const float* pb[4];
#pragma unroll
            for (int s = 0; s < 4; s++) {
                int a = pe[2 * s], b = pe[2 * s + 1];
                pa[s] = (a == 0) ? nd0 : (a == 1) ? nd1 : (a == 2) ? nd2
                      : (a == 3) ? nd3 : (a == 4) ? nd4 : nd5;
                pb[s] = (b == 0) ? nd0 : (b == 1) ? nd1 : (b == 2) ? nd2
                      : (b == 3) ? nd3 : (b == 4) ? nd4 : nd5;
            }

            auto paircomp = [&](int k, uint32_t& hi2, uint32_t& lo2) {
                float s0 = 0.f, s1 = 0.f;
#pragma unroll
                for (int s = 0; s < 4; s++) {
                    float2 A = *(const float2*)(pa[s] + k);
                    float2 B = *(const float2*)(pb[s] + k);
                    float zl = fmaxf(A.x + B.x, 0.f);
                    float zh = fmaxf(A.y + B.y, 0.f);
                    s0 = fmaf(mmv[s], zl, s0);
                    s1 = fmaf(mmv[s], zh, s1);
                }
                hi2 = bf16x2(s0, s1);
                lo2 = bf16x2(s0 - bf_lo(hi2), s1 - bf_hi(hi2));
            };

            char* bufH = smem + SM_AH + buf * 16384;
            char* bufL = smem + SM_AL + buf * 16384;
#pragma unroll
            for (int kk = 0; kk < 2; kk++) {
                const int ks = pkq * 2 + kk;
                char* slotH = bufH + (g_ * 8 + ks) * 512;
                char* slotL = bufL + (g_ * 8 + ks) * 512;
#pragma unroll
                for (int j = 0; j < 4; j++) {
                    uint32_t hA, lA, hC, lC;
                    paircomp(ks * 16 + 2 * j, hA, lA);
                    paircomp(ks * 16 + 2 * j + 8, hC, lC);
                    uint32_t ohA = __shfl_xor_sync(0xffffffffu, hA, 8);
                    uint32_t ohC = __shfl_xor_sync(0xffffffffu, hC, 8);
                    uint32_t olA = __shfl_xor_sync(0xffffffffu, lA, 8);
                    uint32_t olC = __shfl_xor_sync(0xffffffffu, lC, 8);
                    const int p_ = r * 4 + (j ^ ((r >> 1) & 3));
                    if (hiRole) {
                        *(uint4*)(slotH + p_ * 16) = make_uint4(hA, ohA, hC, ohC);
                    } else {
                        *(uint4*)(slotL + p_ * 16) = make_uint4(olA, lA, olC, lC);
                    }
                }
            }
        } else if (prev_t >= 0) {
            // ================= CONSUME tile prev_t from buf^1 =================
            const char* bufH = smem + SM_AH + (buf ^ 1) * 16384;
            const char* bufL = smem + SM_AL + (buf ^ 1) * 16384;

            float acc[2][4][4];
#pragma unroll
            for (int m = 0; m < 2; m++)
#pragma unroll
                for (int nt = 0; nt < 4; nt++)
#pragma unroll
                    for (int j = 0; j < 4; j++) acc[m][nt][j] = 0.f;

#pragma unroll
            for (int ks = 0; ks < 8; ks++) {
                uint4 ah[2], al[2];
#pragma unroll
                for (int m = 0; m < 2; m++) {
                    const int g_ = rg * 2 + m;
                    ah[m] = ((const uint4*)(bufH + (g_ * 8 + ks) * 512))[pos];
                    al[m] = ((const uint4*)(bufL + (g_ * 8 + ks) * 512))[pos];
                }
                const uint4* Bp = (const uint4*)(smem + SM_B + (ks * 16 + cg * 4) * 512);
#pragma unroll
                for (int nt = 0; nt < 4; nt++) {
                    uint4 B = Bp[nt * 32 + lane];
#pragma unroll
                    for (int m = 0; m < 2; m++) {
                        mma_bf16(acc[m][nt], (const uint32_t*)&ah[m], B.x, B.y);
                        mma_bf16(acc[m][nt], (const uint32_t*)&ah[m], B.z, B.w);
                        mma_bf16(acc[m][nt], (const uint32_t*)&al[m], B.x, B.y);
                    }
                }
            }

            float* ob = out + (size_t)prev_t * TILE_M * GD;
#pragma unroll
            for (int m = 0; m < 2; m++) {
                const int r0 = rg * 32 + m * 16 + (lane >> 2);
#pragma unroll
                for (int nt = 0; nt < 4; nt++) {
                    const int c = cg * 32 + nt * 8 + (lane & 3) * 2;
                    *(float2*)(ob + (size_t)r0 * GD + c) = make_float2(acc[m][nt][0], acc[m][nt][1]);
                    *(float2*)(ob + (size_t)(r0 + 8) * GD + c) = make_float2(acc[m][nt][2], acc[m][nt][3]);
                }
            }
        }
        __syncthreads();
        prev_t = t;
        buf ^= 1;
    }

    // ---- drain: consume the last produced tile ----
    if (consumer && prev_t >= 0) {
        const char* bufH = smem + SM_AH + (buf ^ 1) * 16384;
        const char* bufL = smem + SM_AL + (buf ^ 1) * 16384;

        float acc[2][4][4];
#pragma unroll
        for (int m = 0; m < 2; m++)
#pragma unroll
            for (int nt = 0; nt < 4; nt++)
#pragma unroll
                for (int j = 0; j < 4; j++) acc[m][nt][j] = 0.f;

#pragma unroll
        for (int ks = 0; ks < 8; ks++) {
            uint4 ah[2], al[2];
#pragma unroll
            for (int m = 0; m < 2; m++) {
                const int g_ = rg * 2 + m;
                ah[m] = ((const uint4*)(bufH + (g_ * 8 + ks) * 512))[pos];
                al[m] = ((const uint4*)(bufL + (g_ * 8 + ks) * 512))[pos];
            }
            const uint4* Bp = (const uint4*)(smem + SM_B + (ks * 16 + cg * 4) * 512);
#pragma unroll
            for (int nt = 0; nt < 4; nt++) {
                uint4 B = Bp[nt * 32 + lane];
#pragma unroll
                for (int m = 0; m < 2; m++) {
                    mma_bf16(acc[m][nt], (const uint32_t*)&ah[m], B.x, B.y);
                    mma_bf16(acc[m][nt], (const uint32_t*)&ah[m], B.z, B.w);
                    mma_bf16(acc[m][nt], (const uint32_t*)&al[m], B.x, B.y);
                }
            }
        }

        float* ob = out + (size_t)prev_t * TILE_M * GD;
#pragma unroll
        for (int m = 0; m < 2; m++) {
            const int r0 = rg * 32 + m * 16 + (lane >> 2);
#pragma unroll
            for (int nt = 0; nt < 4; nt++) {
                const int c = cg * 32 + nt * 8 + (lane & 3) * 2;
                *(float2*)(ob + (size_t)r0 * GD + c) = make_float2(acc[m][nt][0], acc[m][nt][1]);
                *(float2*)(ob + (size_t)(r0 + 8) * GD + c) = make_float2(acc[m][nt][2], acc[m][nt][3]);
            }
        }
    }
}

// ---------------------------------------------------------------------------
extern "C" void kernel_launch(void* const* d_in, const int* in_sizes, int n_in,
                              void* d_out, int out_size) {
    const int*   archs    = (const int*)  d_in[0];
    const float* init_emb = (const float*)d_in[1];
    const float* op_emb   = (const float*)d_in[2];
    const float* xw       = (const float*)d_in[3];
    const float* xb       = (const float*)d_in[4];
    const float* w1       = (const float*)d_in[5];
    const float* w2       = (const float*)d_in[6];
    float* out = (float*)d_out;

    cudaFuncSetAttribute(gcn_main_kernel,
                         cudaFuncAttributeMaxDynamicSharedMemorySize, SMEM_BYTES);

    gcn_prep_kernel<<<33, 256>>>(init_emb, op_emb, xw, xb, w1, w2);
    gcn_main_kernel<<<NCTAS, 512, SMEM_BYTES>>>(archs, out);
}

// round 11
// speedup vs baseline: 1.5028x; 1.5028x over previous
#include <cuda_runtime.h>
#include <cuda_bf16.h>
#include <cstdint>

// ---------------------------------------------------------------------------
// GCNArchEmbedder via mma.sync bf16 (HMMA), 3-pass hi/lo fp32 emulation.
// R11: R9 persistent warp-specialized kernel (producer = R9's conflict-free
//   tab pattern) + named-barrier produce/consume protocol (bar.arrive /
//   bar.sync per buffer) replacing the per-tile __syncthreads rendezvous.
// ---------------------------------------------------------------------------

#define NUM_PRIM   8
#define OPD        48
#define OPH        48
#define GD         128
#define ROWS       65536
#define TILE_M     64
#define NTILES     (ROWS / TILE_M)     // 1024
#define NCTAS      148
#define TPAD       132

// table rows: 0..7 U0''[p] (=U0+Uc), 8..15 U1[p], 16..17 H1init
__device__ float g_tab[18 * GD];
// W2 fragments: idx = (ks*16 + ntile)*32 + lane ; {b0hi, b1hi, b0lo, b1lo}
__device__ uint4 g_bfrag[4096];

typedef unsigned long long ull;
__device__ __forceinline__ ull pk2(float lo, float hi) {
    ull r; asm("mov.b64 %0, {%1, %2};" : "=l"(r) : "f"(lo), "f"(hi)); return r;
}
__device__ __forceinline__ void unpk2(float& lo, float& hi, ull v) {
    asm("mov.b64 {%0, %1}, %2;" : "=f"(lo), "=f"(hi) : "l"(v));
}
__device__ __forceinline__ ull add2(ull a, ull b) {
    ull r; asm("add.rn.f32x2 %0, %1, %2;" : "=l"(r) : "l"(a), "l"(b)); return r;
}
__device__ __forceinline__ ull mul2(ull a, ull b) {
    ull r; asm("mul.rn.f32x2 %0, %1, %2;" : "=l"(r) : "l"(a), "l"(b)); return r;
}
__device__ __forceinline__ void fma2(ull& d, ull a, ull b) {
    asm("fma.rn.f32x2 %0, %1, %2, %0;" : "+l"(d) : "l"(a), "l"(b));
}
// low half = first arg (k-even element)
__device__ __forceinline__ uint32_t bf16x2(float lo, float hi) {
    uint32_t r; asm("cvt.rn.bf16x2.f32 %0, %1, %2;" : "=r"(r) : "f"(hi), "f"(lo)); return r;
}
__device__ __forceinline__ float bf_lo(uint32_t u) { return __uint_as_float(u << 16); }
__device__ __forceinline__ float bf_hi(uint32_t u) { return __uint_as_float(u & 0xffff0000u); }

__device__ __forceinline__ void mma_bf16(float* d, const uint32_t* a,
                                         uint32_t b0, uint32_t b1) {
    asm volatile(
        "mma.sync.aligned.m16n8k16.row.col.f32.bf16.bf16.f32 "
        "{%0,%1,%2,%3}, {%4,%5,%6,%7}, {%8,%9}, {%0,%1,%2,%3};"
        : "+f"(d[0]), "+f"(d[1]), "+f"(d[2]), "+f"(d[3])
        : "r"(a[0]), "r"(a[1]), "r"(a[2]), "r"(a[3]), "r"(b0), "r"(b1));
}

__device__ __forceinline__ uint32_t smem_u32(const void* p) {
    uint32_t a;
    asm("{ .reg .u64 t; cvta.to.shared.u64 t, %1; cvt.u32.u64 %0, t; }" : "=r"(a) : "l"(p));
    return a;
}
__device__ __forceinline__ void cp_async16(uint32_t saddr, const void* g) {
    asm volatile("cp.async.cg.shared.global [%0], [%1], 16;" :: "r"(saddr), "l"(g) : "memory");
}

// named-barrier produce/consume (count = all 512 threads)
#define BAR_SYNC(id)   asm volatile("bar.sync %0, 512;"   :: "r"(id) : "memory")
#define BAR_ARRIVE(id) asm volatile("bar.arrive %0, 512;" :: "r"(id) : "memory")
#define BAR_EMPTY0 1
#define BAR_EMPTY1 2
#define BAR_FULL0  3
#define BAR_FULL1  4

// ---------------------------------------------------------------------------
// Prep kernel, <<<33, 256>>> (wide & shallow):
//   blocks 0..15 : (p, which) -> U0''[p] / U1[p]
//   block  16    : H1init rows
//   blocks 17..32: W2 fragment pack
// ---------------------------------------------------------------------------
__global__ void gcn_prep_kernel(const float* __restrict__ init_emb,
                                const float* __restrict__ op_emb,
                                const float* __restrict__ xw,
                                const float* __restrict__ xb,
                                const float* __restrict__ w1,
                                const float* __restrict__ w2) {
    const int b = blockIdx.x;
    const int t = threadIdx.x;

    if (b < 16) {                      // row (which*8 + p) of g_tab
        const int p = b >> 1, which = b & 1;
        __shared__ float T[OPH];
        if (t < OPH) {
            float s0 = 0.f, s1 = 0.f, s2 = 0.f, s3 = 0.f;
            const int db = which * OPD;
            for (int d = 0; d < OPD; d += 4) {
                s0 = fmaf(op_emb[p * OPD + d],     xw[(db + d) * OPH + t],     s0);
                s1 = fmaf(op_emb[p * OPD + d + 1], xw[(db + d + 1) * OPH + t], s1);
                s2 = fmaf(op_emb[p * OPD + d + 2], xw[(db + d + 2) * OPH + t], s2);
                s3 = fmaf(op_emb[p * OPD + d + 3], xw[(db + d + 3) * OPH + t], s3);
            }
            T[t] = (s0 + s1) + (s2 + s3);
        }
        __syncthreads();
        if (t < GD) {
            float s0 = 0.f, s1 = 0.f, u0 = 0.f, u1 = 0.f;
            for (int h = 0; h < OPH; h += 2) {
                float wa = w1[h * GD + t], wb = w1[(h + 1) * GD + t];
                s0 = fmaf(T[h],     wa, s0);
                s1 = fmaf(T[h + 1], wb, s1);
                u0 = fmaf(xb[h],     wa, u0);
                u1 = fmaf(xb[h + 1], wb, u1);
            }
            g_tab[(which * 8 + p) * GD + t] = s0 + s1 + (which == 0 ? (u0 + u1) : 0.f);
        }
    } else if (b == 16) {              // init rows
        __shared__ float Y[2][OPH];
        if (t < 96) {
            const int kk = t / 48, h = t % 48;
            float s0 = xb[h], s1 = 0.f, s2 = 0.f, s3 = 0.f;
            for (int d = 0; d < 2 * OPD; d += 4) {
                s0 = fmaf(init_emb[kk * 2 * OPD + d],     xw[d * OPH + h],       s0);
                s1 = fmaf(init_emb[kk * 2 * OPD + d + 1], xw[(d + 1) * OPH + h], s1);
                s2 = fmaf(init_emb[kk * 2 * OPD + d + 2], xw[(d + 2) * OPH + h], s2);
                s3 = fmaf(init_emb[kk * 2 * OPD + d + 3], xw[(d + 3) * OPH + h], s3);
            }
            Y[kk][h] = (s0 + s1) + (s2 + s3);
        }
        __syncthreads();
        const int kk = t >> 7, f = t & 127;
        float s0 = 0.f, s1 = 0.f;
        for (int h = 0; h < OPH; h += 2) {
            s0 = fmaf(Y[kk][h],     w1[h * GD + f],       s0);
            s1 = fmaf(Y[kk][h + 1], w1[(h + 1) * GD + f], s1);
        }
        g_tab[(16 + kk) * GD + f] = s0 + s1;
    } else {                           // W2 pack
        const int idx = (b - 17) * 256 + t;  // 0..4095
        const int lane = idx & 31;
        const int nt   = (idx >> 5) & 15;
        const int ks   = idx >> 9;
        const int k0 = ks * 16 + (lane & 3) * 2;
        const int n  = nt * 8 + (lane >> 2);
        float w00 = w2[k0 * GD + n];
        float w01 = w2[(k0 + 1) * GD + n];
        float w10 = w2[(k0 + 8) * GD + n];
        float w11 = w2[(k0 + 9) * GD + n];
        uint32_t b0h = bf16x2(w00, w01);
        uint32_t b1h = bf16x2(w10, w11);
        uint32_t b0l = bf16x2(w00 - bf_lo(b0h), w01 - bf_hi(b0h));
        uint32_t b1l = bf16x2(w10 - bf_lo(b1h), w11 - bf_hi(b1h));
        g_bfrag[idx] = make_uint4(b0h, b1h, b0l, b1l);
    }
}

// ---------------------------------------------------------------------------
// Persistent main kernel. smem byte layout:
//   AH[2]  0      (2 x 16384)   [g4][ks8][pos32] uint4, XOR-swizzled pos
//   AL[2]  32768  (2 x 16384)
//   B      65536  (65536)       [ks8][nt16][lane32] uint4 {b0h,b1h,b0l,b1l}
//   tab    131072 (9504)        18 x TPAD floats
// total 140576 B -> 1 CTA/SM.
// ---------------------------------------------------------------------------
#define SM_AH    0
#define SM_AL    32768
#define SM_B     65536
#define SM_TAB   131072
#define SMEM_BYTES 140576

__global__ void __launch_bounds__(512, 1)
gcn_main_kernel(const int* __restrict__ archs, float* __restrict__ out) {
    extern __shared__ char smem[];
    float* tab = (float*)(smem + SM_TAB);

    const int tid  = threadIdx.x;
    const int wid  = tid >> 5;
    const int lane = tid & 31;
    const bool consumer = (wid < 8);

    // ---- one-time staging: B frags (cp.async) + tables ----
    {
        const uint32_t bsm = smem_u32(smem + SM_B);
#pragma unroll
        for (int i = 0; i < 8; i++)
            cp_async16(bsm + (tid + 512 * i) * 16, &g_bfrag[tid + 512 * i]);
        asm volatile("cp.async.commit_group;" ::: "memory");
        for (int idx = tid; idx < 18 * GD; idx += 512)
            tab[(idx >> 7) * TPAD + (idx & 127)] = g_tab[idx];
        asm volatile("cp.async.wait_group 0;" ::: "memory");
    }
    __syncthreads();

    // consumer constants
    const int rg = (wid >> 2) & 1;
    const int cg = wid & 3;
    const int pos = (lane & 28) | ((lane ^ (lane >> 3)) & 3);
    // producer constants
    const int ptid = tid - 256;
    const int prow = ptid & 63;
    const int pkq  = (ptid >> 6) & 3;

    // consumers pre-signal both buffers empty
    if (consumer) {
        BAR_ARRIVE(BAR_EMPTY0);
        BAR_ARRIVE(BAR_EMPTY1);
    }

    int parity = 0;
    for (int t = blockIdx.x; t < NTILES; t += NCTAS, parity ^= 1) {
        if (!consumer) {
            // ================= PRODUCE tile t into buf[parity] =================
            BAR_SYNC(parity ? BAR_EMPTY1 : BAR_EMPTY0);

            const int row = prow;
            const int g_  = row >> 4;
            const int r   = row & 7;
            const bool hiRole = ((row & 8) == 0);

            const int4* ap = (const int4*)(archs + ((size_t)t * TILE_M + row) * 16);
            int4 a0v = __ldg(ap), a1v = __ldg(ap + 1);
            int4 a2v = __ldg(ap + 2), a3v = __ldg(ap + 3);
            int pe[8] = {a0v.x, a0v.y, a0v.z, a0v.w, a1v.x, a1v.y, a1v.z, a1v.w};
            int oe[8] = {a2v.x, a2v.y, a2v.z, a2v.w, a3v.x, a3v.y, a3v.z, a3v.w};

            ull A2[4][6];
            float mmv[4];
#pragma unroll
            for (int s = 0; s < 4; s++) {
#pragma unroll
                for (int j = 0; j < 6; j++) {
                    float v = (pe[2 * s] == j ? 1.f : 0.f) + (pe[2 * s + 1] == j ? 1.f : 0.f);
                    A2[s][j] = pk2(v, v);
                }
                float c = 0.f;
#pragma unroll
                for (int e = 0; e < 8; e++) c += (pe[e] == s + 2) ? 1.f : 0.f;
                mmv[s] = c * 0.25f;
            }

            const float* qa0 = tab + oe[0] * TPAD;
            const float* qb0 = tab + (8 + oe[1]) * TPAD;
            const float* qa1 = tab + oe[2] * TPAD;
            const float* qb1 = tab + (8 + oe[3]) * TPAD;
            const float* qa2 = tab + oe[4] * TPAD;
            const float* qb2 = tab + (8 + oe[5]) * TPAD;
            const float* qa3 = tab + oe[6] * TPAD;
            const float* qb3 = tab + (8 + oe[7]) * TPAD;
            const float* p0 = tab + 16 * TPAD;
            const float* p1 = tab + 17 * TPAD;

            auto paircomp = [&](int k, uint32_t& hi2, uint32_t& lo2) {
                ull h0 = *(const ull*)(p0 + k);
                ull h1 = *(const ull*)(p1 + k);
                ull h2 = add2(*(const ull*)(qa0 + k), *(const ull*)(qb0 + k));
                ull h3 = add2(*(const ull*)(qa1 + k), *(const ull*)(qb1 + k));
                ull h4 = add2(*(const ull*)(qa2 + k), *(const ull*)(qb2 + k));
                ull h5 = add2(*(const ull*)(qa3 + k), *(const ull*)(qb3 + k));
                float s0 = 0.f, s1 = 0.f;
#pragma unroll
                for (int s = 0; s < 4; s++) {
                    ull z = mul2(A2[s][0], h0);
                    fma2(z, A2[s][1], h1);
                    fma2(z, A2[s][2], h2);
                    fma2(z, A2[s][3], h3);
                    fma2(z, A2[s][4], h4);
                    fma2(z, A2[s][5], h5);
                    float zl, zh; unpk2(zl, zh, z);
                    zl = fmaxf(zl, 0.f);
                    zh = fmaxf(zh, 0.f);
                    s0 = fmaf(mmv[s], zl, s0);
                    s1 = fmaf(mmv[s], zh, s1);
                }
                hi2 = bf16x2(s0, s1);
                lo2 = bf16x2(s0 - bf_lo(hi2), s1 - bf_hi(hi2));
            };

            char* bufH = smem + SM_AH + parity * 16384;
            char* bufL = smem + SM_AL + parity * 16384;
#pragma unroll
            for (int kk = 0; kk < 2; kk++) {
                const int ks = pkq * 2 + kk;
                char* slotH = bufH + (g_ * 8 + ks) * 512;
                char* slotL = bufL + (g_ * 8 + ks) * 512;
#pragma unroll
                for (int j = 0; j < 4; j++) {
                    uint32_t hA, lA, hC, lC;
                    paircomp(ks * 16 + 2 * j, hA, lA);
                    paircomp(ks * 16 + 2 * j + 8, hC, lC);
                    uint32_t ohA = __shfl_xor_sync(0xffffffffu, hA, 8);
                    uint32_t ohC = __shfl_xor_sync(0xffffffffu, hC, 8);
                    uint32_t olA = __shfl_xor_sync(0xffffffffu, lA, 8);
                    uint32_t olC = __shfl_xor_sync(0xffffffffu, lC, 8);
                    const int p_ = r * 4 + (j ^ ((r >> 1) & 3));
                    if (hiRole) {
                        *(uint4*)(slotH + p_ * 16) = make_uint4(hA, ohA, hC, ohC);
                    } else {
                        *(uint4*)(slotL + p_ * 16) = make_uint4(olA, lA, olC, lC);
                    }
                }
            }
            BAR_ARRIVE(parity ? BAR_FULL1 : BAR_FULL0);
        } else {
            // ================= CONSUME tile t from buf[parity] =================
            BAR_SYNC(parity ? BAR_FULL1 : BAR_FULL0);

            const char* bufH = smem + SM_AH + parity * 16384;
            const char* bufL = smem + SM_AL + parity * 16384;

            float acc[2][4][4];
#pragma unroll
            for (int m = 0; m < 2; m++)
#pragma unroll
                for (int nt = 0; nt < 4; nt++)
#pragma unroll
                    for (int j = 0; j < 4; j++) acc[m][nt][j] = 0.f;

#pragma unroll
            for (int ks = 0; ks < 8; ks++) {
                uint4 ah[2], al[2];
#pragma unroll
                for (int m = 0; m < 2; m++) {
                    const int g_ = rg * 2 + m;
                    ah[m] = ((const uint4*)(bufH + (g_ * 8 + ks) * 512))[pos];
                    al[m] = ((const uint4*)(bufL + (g_ * 8 + ks) * 512))[pos];
                }
                const uint4* Bp = (const uint4*)(smem + SM_B + (ks * 16 + cg * 4) * 512);
#pragma unroll
                for (int nt = 0; nt < 4; nt++) {
                    uint4 B = Bp[nt * 32 + lane];
#pragma unroll
                    for (int m = 0; m < 2; m++) {
                        mma_bf16(acc[m][nt], (const uint32_t*)&ah[m], B.x, B.y);
                        mma_bf16(acc[m][nt], (const uint32_t*)&ah[m], B.z, B.w);
                        mma_bf16(acc[m][nt], (const uint32_t*)&al[m], B.x, B.y);
                    }
                }
            }
            BAR_ARRIVE(parity ? BAR_EMPTY1 : BAR_EMPTY0);

            float* ob = out + (size_t)t * TILE_M * GD;
#pragma unroll
            for (int m = 0; m < 2; m++) {
                const int r0 = rg * 32 + m * 16 + (lane >> 2);
#pragma unroll
                for (int nt = 0; nt < 4; nt++) {
                    const int c = cg * 32 + nt * 8 + (lane & 3) * 2;
                    *(float2*)(ob + (size_t)r0 * GD + c) = make_float2(acc[m][nt][0], acc[m][nt][1]);
                    *(float2*)(ob + (size_t)(r0 + 8) * GD + c) = make_float2(acc[m][nt][2], acc[m][nt][3]);
                }
            }
        }
    }
}

// ---------------------------------------------------------------------------
extern "C" void kernel_launch(void* const* d_in, const int* in_sizes, int n_in,
                              void* d_out, int out_size) {
    const int*   archs    = (const int*)  d_in[0];
    const float* init_emb = (const float*)d_in[1];
    const float* op_emb   = (const float*)d_in[2];
    const float* xw       = (const float*)d_in[3];
    const float* xb       = (const float*)d_in[4];
    const float* w1       = (const float*)d_in[5];
    const float* w2       = (const float*)d_in[6];
    float* out = (float*)d_out;

    cudaFuncSetAttribute(gcn_main_kernel,
                         cudaFuncAttributeMaxDynamicSharedMemorySize, SMEM_BYTES);

    gcn_prep_kernel<<<33, 256>>>(init_emb, op_emb, xw, xb, w1, w2);
    gcn_main_kernel<<<NCTAS, 512, SMEM_BYTES>>>(archs, out);
}